// round 1
// baseline (speedup 1.0000x reference)
#include <cuda_runtime.h>

// Problem dims (fixed per reference)
#define T_DIM 2048
#define B_DIM 8
#define D_DIM 1024
#define C_DIM (B_DIM * D_DIM)   // 8192 channels
#define M_DIM (T_DIM * B_DIM)   // 16384 GEMM rows
#define N_DIM (2 * D_DIM)       // 2048 combined outputs (alpha | v)
#define K_DIM D_DIM             // 1024

// Scratch for gate/value activations, [t][b][e] layout (== [m][e], m = t*B+b)
__device__ float g_alpha[(size_t)M_DIM * D_DIM];
__device__ float g_v[(size_t)M_DIM * D_DIM];

// ---------------- packed f32x2 helpers (sm_103a) ----------------
__device__ __forceinline__ unsigned long long pack2(float x, float y) {
    unsigned long long r;
    asm("mov.b64 %0, {%1, %2};" : "=l"(r) : "f"(x), "f"(y));
    return r;
}
__device__ __forceinline__ void unpack2(unsigned long long p, float& x, float& y) {
    asm("mov.b64 {%0, %1}, %2;" : "=f"(x), "=f"(y) : "l"(p));
}
__device__ __forceinline__ void fma2(unsigned long long& d, unsigned long long a,
                                     unsigned long long b) {
    asm("fma.rn.f32x2 %0, %1, %2, %0;" : "+l"(d) : "l"(a), "l"(b));
}

__device__ __forceinline__ float fast_sigmoid(float z) {
    return __fdividef(1.0f, 1.0f + __expf(-z));
}

// ---------------- Kernel 1: dual GEMM + bias (+sigmoid for alpha) ----------------
// C[m, n] = sum_k x[m, k] * W[n, k]   (both K-major)
// Tile: BM=64, BN=128, BK=16, 256 threads, thread tile 4(m) x 8(n) via f32x2.
__global__ __launch_bounds__(256, 2)
void gemm_gates_kernel(const float* __restrict__ x,
                       const float* __restrict__ W_alpha,
                       const float* __restrict__ b_alpha,
                       const float* __restrict__ W_v,
                       const float* __restrict__ b_v)
{
    __shared__ float As[2][16][64];
    __shared__ float Bs[2][16][128];

    const int tid   = threadIdx.x;
    const int mBase = blockIdx.y * 64;
    const int nBase = blockIdx.x * 128;

    const bool  isAlpha = (nBase < D_DIM);
    const float* __restrict__ Wmat = isAlpha ? W_alpha : W_v;
    const int   rowW = isAlpha ? nBase : (nBase - D_DIM);

    // A loader: one float4 per thread; lanes 0..31 cover rows 0..7 contiguously
    const int ar  = tid >> 2;   // 0..63
    const int ak4 = tid & 3;    // 0..3
    const float* aptr = x + (size_t)(mBase + ar) * K_DIM + ak4 * 4;

    // B loader: two float4 per thread (idx = tid and tid+256)
    const int br0  = tid >> 2;           // 0..63
    const int bk40 = tid & 3;
    const int br1  = br0 + 64;           // 64..127
    const int bk41 = bk40;
    const float* bptr0 = Wmat + (size_t)(rowW + br0) * K_DIM + bk40 * 4;
    const float* bptr1 = Wmat + (size_t)(rowW + br1) * K_DIM + bk41 * 4;

    const int ty = tid >> 4;   // 0..15 (m group)
    const int tx = tid & 15;   // 0..15 (n group)

    unsigned long long acc[4][4];
#pragma unroll
    for (int i = 0; i < 4; ++i)
#pragma unroll
        for (int p = 0; p < 4; ++p) acc[i][p] = 0ull;

    // preload k-tile 0
    {
        float4 pa  = *(const float4*)(aptr);
        float4 pb0 = *(const float4*)(bptr0);
        float4 pb1 = *(const float4*)(bptr1);
        As[0][ak4 * 4 + 0][ar] = pa.x;
        As[0][ak4 * 4 + 1][ar] = pa.y;
        As[0][ak4 * 4 + 2][ar] = pa.z;
        As[0][ak4 * 4 + 3][ar] = pa.w;
        Bs[0][bk40 * 4 + 0][br0] = pb0.x;
        Bs[0][bk40 * 4 + 1][br0] = pb0.y;
        Bs[0][bk40 * 4 + 2][br0] = pb0.z;
        Bs[0][bk40 * 4 + 3][br0] = pb0.w;
        Bs[0][bk41 * 4 + 0][br1] = pb1.x;
        Bs[0][bk41 * 4 + 1][br1] = pb1.y;
        Bs[0][bk41 * 4 + 2][br1] = pb1.z;
        Bs[0][bk41 * 4 + 3][br1] = pb1.w;
    }
    __syncthreads();

    const int NKT = K_DIM / 16;   // 64
    for (int kt = 0; kt < NKT; ++kt) {
        const int cur = kt & 1;
        float4 pa, pb0, pb1;
        const bool more = (kt + 1 < NKT);
        if (more) {
            const int ko = (kt + 1) * 16;
            pa  = *(const float4*)(aptr + ko);
            pb0 = *(const float4*)(bptr0 + ko);
            pb1 = *(const float4*)(bptr1 + ko);
        }
#pragma unroll
        for (int k = 0; k < 16; ++k) {
            const float4 av  = *(const float4*)&As[cur][k][ty * 4];
            const ulonglong2 bq0 = *(const ulonglong2*)&Bs[cur][k][tx * 8];
            const ulonglong2 bq1 = *(const ulonglong2*)&Bs[cur][k][tx * 8 + 4];
            const unsigned long long bp0 = bq0.x, bp1 = bq0.y;
            const unsigned long long bp2 = bq1.x, bp3 = bq1.y;
            const unsigned long long ap0 = pack2(av.x, av.x);
            const unsigned long long ap1 = pack2(av.y, av.y);
            const unsigned long long ap2 = pack2(av.z, av.z);
            const unsigned long long ap3 = pack2(av.w, av.w);
            fma2(acc[0][0], ap0, bp0); fma2(acc[0][1], ap0, bp1);
            fma2(acc[0][2], ap0, bp2); fma2(acc[0][3], ap0, bp3);
            fma2(acc[1][0], ap1, bp0); fma2(acc[1][1], ap1, bp1);
            fma2(acc[1][2], ap1, bp2); fma2(acc[1][3], ap1, bp3);
            fma2(acc[2][0], ap2, bp0); fma2(acc[2][1], ap2, bp1);
            fma2(acc[2][2], ap2, bp2); fma2(acc[2][3], ap2, bp3);
            fma2(acc[3][0], ap3, bp0); fma2(acc[3][1], ap3, bp1);
            fma2(acc[3][2], ap3, bp2); fma2(acc[3][3], ap3, bp3);
        }
        if (more) {
            const int nxt = cur ^ 1;
            As[nxt][ak4 * 4 + 0][ar] = pa.x;
            As[nxt][ak4 * 4 + 1][ar] = pa.y;
            As[nxt][ak4 * 4 + 2][ar] = pa.z;
            As[nxt][ak4 * 4 + 3][ar] = pa.w;
            Bs[nxt][bk40 * 4 + 0][br0] = pb0.x;
            Bs[nxt][bk40 * 4 + 1][br0] = pb0.y;
            Bs[nxt][bk40 * 4 + 2][br0] = pb0.z;
            Bs[nxt][bk40 * 4 + 3][br0] = pb0.w;
            Bs[nxt][bk41 * 4 + 0][br1] = pb1.x;
            Bs[nxt][bk41 * 4 + 1][br1] = pb1.y;
            Bs[nxt][bk41 * 4 + 2][br1] = pb1.z;
            Bs[nxt][bk41 * 4 + 3][br1] = pb1.w;
            __syncthreads();
        }
    }

    // epilogue: bias (+sigmoid for alpha half), write scratch [m][e]
    const float* __restrict__ bias = isAlpha ? b_alpha : b_v;
    float* __restrict__ dst = isAlpha ? g_alpha : g_v;
#pragma unroll
    for (int i = 0; i < 4; ++i) {
        const int m = mBase + ty * 4 + i;
        float* drow = dst + (size_t)m * D_DIM + rowW + tx * 8;
#pragma unroll
        for (int p = 0; p < 4; ++p) {
            float lo, hi;
            unpack2(acc[i][p], lo, hi);
            const int nl = rowW + tx * 8 + 2 * p;
            lo += bias[nl];
            hi += bias[nl + 1];
            if (isAlpha) { lo = fast_sigmoid(lo); hi = fast_sigmoid(hi); }
            float2 st;
            st.x = lo; st.y = hi;
            *(float2*)(drow + 2 * p) = st;
        }
    }
}

// ---------------- Kernel 2: per-channel scan over time ----------------
// One thread per (b, d) channel; prefetch depth 8 to hide DRAM latency.
__global__ __launch_bounds__(64)
void scan_kernel(const float* __restrict__ h0,
                 float* __restrict__ out,   // [T, B, D]
                 float* __restrict__ hs,    // [T+1, B, D] or null
                 int write_h)
{
    const int ch = blockIdx.x * 64 + threadIdx.x;
    const float* __restrict__ A = g_alpha + ch;
    const float* __restrict__ V = g_v + ch;

    float h = h0[ch];
    if (write_h) hs[ch] = h;   // h[0] = h0

    constexpr int P = 8;
    float ab[P], vb[P];
#pragma unroll
    for (int i = 0; i < P; ++i) {
        ab[i] = A[i * C_DIM];
        vb[i] = V[i * C_DIM];
    }

    for (int t = 0; t < T_DIM; t += P) {
#pragma unroll
        for (int i = 0; i < P; ++i) {
            const float a = ab[i];
            const float v = vb[i];
            const int tn = t + i + P;
            if (tn < T_DIM) {
                ab[i] = A[tn * C_DIM];
                vb[i] = V[tn * C_DIM];
            }
            h = fmaf(a, h - v, v);                 // a*h + (1-a)*v
            const float sg = fast_sigmoid(h);
            out[(t + i) * C_DIM + ch] = h * h * sg;  // h * silu(h)
            if (write_h) hs[(t + i + 1) * C_DIM + ch] = h;
        }
    }
}

extern "C" void kernel_launch(void* const* d_in, const int* in_sizes, int n_in,
                              void* d_out, int out_size) {
    const float* x  = (const float*)d_in[0];
    const float* h0 = (const float*)d_in[1];
    const float* Wa = (const float*)d_in[2];
    const float* ba = (const float*)d_in[3];
    const float* Wv = (const float*)d_in[4];
    const float* bv = (const float*)d_in[5];

    float* out = (float*)d_out;
    const long long out_elems = (long long)T_DIM * C_DIM;            // 16,777,216
    const long long h_elems   = (long long)(T_DIM + 1) * C_DIM;      // 16,785,408
    const int write_h = (out_size >= (long long)(out_elems + h_elems)) ? 1 : 0;
    float* hs = out + out_elems;

    dim3 g1(N_DIM / 128, M_DIM / 64);   // (16, 256)
    gemm_gates_kernel<<<g1, 256>>>(x, Wa, ba, Wv, bv);
    scan_kernel<<<C_DIM / 64, 64>>>(h0, out, hs, write_h);
}

// round 3
// speedup vs baseline: 3.6851x; 3.6851x over previous
#include <cuda_runtime.h>
#include <cuda_bf16.h>
#include <cstdint>

#define T_DIM 2048
#define B_DIM 8
#define D_DIM 1024
#define C_DIM 8192              // B*D channels
#define M_DIM 16384             // T*B gemm rows
#define N_DIM 2048              // alpha|v concat
#define K_DIM 1024

#define SEG 32
#define SLEN 64                 // T / SEG

// ---------------- device scratch ----------------
__device__ float g_alpha[(size_t)M_DIM * D_DIM];
__device__ float g_v[(size_t)M_DIM * D_DIM];
__device__ __nv_bfloat16 g_xhi[(size_t)M_DIM * K_DIM];
__device__ __nv_bfloat16 g_xlo[(size_t)M_DIM * K_DIM];
__device__ __nv_bfloat16 g_whi[(size_t)N_DIM * K_DIM];
__device__ __nv_bfloat16 g_wlo[(size_t)N_DIM * K_DIM];
__device__ float g_P[SEG * C_DIM];
__device__ float g_Q[SEG * C_DIM];
__device__ float g_hb[(SEG + 1) * C_DIM];

// ---------------- helpers ----------------
__device__ __forceinline__ uint32_t smem_u32(const void* p) {
    uint32_t a;
    asm("{ .reg .u64 t; cvta.to.shared.u64 t, %1; cvt.u32.u64 %0, t; }" : "=r"(a) : "l"(p));
    return a;
}

__device__ __forceinline__ float fast_sigmoid(float z) {
    return __fdividef(1.0f, 1.0f + __expf(-z));
}

#define LDSM4(r, addr) \
    asm volatile("ldmatrix.sync.aligned.m8n8.x4.shared.b16 {%0,%1,%2,%3}, [%4];" \
        : "=r"((r)[0]), "=r"((r)[1]), "=r"((r)[2]), "=r"((r)[3]) : "r"(addr))

#define MMA16816(c, a, b0, b1) \
    asm volatile("mma.sync.aligned.m16n8k16.row.col.f32.bf16.bf16.f32 " \
        "{%0,%1,%2,%3}, {%4,%5,%6,%7}, {%8,%9}, {%0,%1,%2,%3};" \
        : "+f"((c)[0]), "+f"((c)[1]), "+f"((c)[2]), "+f"((c)[3]) \
        : "r"((a)[0]), "r"((a)[1]), "r"((a)[2]), "r"((a)[3]), "r"(b0), "r"(b1))

// ---------------- split kernels (f32 -> bf16 hi + lo) ----------------
__device__ __forceinline__ void split_store(float4 f, __nv_bfloat16* hi, __nv_bfloat16* lo,
                                            size_t i) {
    __nv_bfloat16 h0 = __float2bfloat16_rn(f.x), h1 = __float2bfloat16_rn(f.y);
    __nv_bfloat16 h2 = __float2bfloat16_rn(f.z), h3 = __float2bfloat16_rn(f.w);
    __nv_bfloat16 l0 = __float2bfloat16_rn(f.x - __bfloat162float(h0));
    __nv_bfloat16 l1 = __float2bfloat16_rn(f.y - __bfloat162float(h1));
    __nv_bfloat16 l2 = __float2bfloat16_rn(f.z - __bfloat162float(h2));
    __nv_bfloat16 l3 = __float2bfloat16_rn(f.w - __bfloat162float(h3));
    __nv_bfloat162* H = (__nv_bfloat162*)(hi + i);
    __nv_bfloat162* L = (__nv_bfloat162*)(lo + i);
    H[0] = __halves2bfloat162(h0, h1);
    H[1] = __halves2bfloat162(h2, h3);
    L[0] = __halves2bfloat162(l0, l1);
    L[1] = __halves2bfloat162(l2, l3);
}

__global__ __launch_bounds__(256) void split_x_kernel(const float* __restrict__ x) {
    size_t i = ((size_t)blockIdx.x * 256 + threadIdx.x) * 4;
    float4 f = *(const float4*)(x + i);
    split_store(f, g_xhi, g_xlo, i);
}

__global__ __launch_bounds__(256) void split_w_kernel(const float* __restrict__ Wa,
                                                      const float* __restrict__ Wv) {
    size_t i = ((size_t)blockIdx.x * 256 + threadIdx.x) * 4;
    size_t n = i >> 10;
    const float* src = (n < D_DIM) ? (Wa + i) : (Wv + (i - (size_t)D_DIM * K_DIM));
    float4 f = *(const float4*)src;
    split_store(f, g_whi, g_wlo, i);
}

// ---------------- HMMA GEMM ----------------
// C[m,n] = sum over 3 segments: xhi*whi + xlo*whi + xhi*wlo, fp32 accum.
// BM=128, BN=128, BK=32, 256 threads (8 warps, 64x32 warp tiles), 3-stage cp.async.
#define BK 32
#define NKK 96                       // 3 segments * (1024/32)
#define ASTG (128 * BK * 2)          // 8192 B
#define STAGE_BYTES (2 * ASTG)       // A + B = 16384 B
#define GSMEM (3 * STAGE_BYTES + 128)

// smem chunk index (16B units) with xor swizzle for conflict-free LDSM
__device__ __forceinline__ uint32_t chunk_off(int r, int kb) {
    return (uint32_t)((r * 4 + (kb ^ ((r >> 1) & 3))) * 16);
}

__device__ __forceinline__ void load_stage(uint32_t smBase, int slot,
                                           const __nv_bfloat16* Asrc,
                                           const __nv_bfloat16* Bsrc, int tid) {
    uint32_t sA = smBase + (uint32_t)slot * STAGE_BYTES;
    uint32_t sB = sA + ASTG;
#pragma unroll
    for (int j = 0; j < 2; ++j) {
        int idx = tid + j * 256;
        int r = idx >> 2, cb = idx & 3;
        const char* gp = (const char*)(Asrc + (size_t)r * K_DIM) + cb * 16;
        asm volatile("cp.async.cg.shared.global [%0], [%1], 16;"
                     :: "r"(sA + chunk_off(r, cb)), "l"(gp));
    }
#pragma unroll
    for (int j = 0; j < 2; ++j) {
        int idx = tid + j * 256;
        int r = idx >> 2, cb = idx & 3;
        const char* gp = (const char*)(Bsrc + (size_t)r * K_DIM) + cb * 16;
        asm volatile("cp.async.cg.shared.global [%0], [%1], 16;"
                     :: "r"(sB + chunk_off(r, cb)), "l"(gp));
    }
    asm volatile("cp.async.commit_group;" ::: "memory");
}

__global__ __launch_bounds__(256, 2)
void gemm_hmma_kernel(const float* __restrict__ b_alpha, const float* __restrict__ b_v) {
    extern __shared__ char smem[];
    uint32_t smBase = (smem_u32(smem) + 127u) & ~127u;

    const int tid = threadIdx.x;
    const int l = tid & 31, wid = tid >> 5;
    const int warpM = (wid & 1) * 64;
    const int warpN = (wid >> 1) * 32;
    const int mBase = blockIdx.y * 128;
    const int nBase = blockIdx.x * 128;
    const bool isA = (nBase < D_DIM);
    const int ncol0 = isA ? nBase : (nBase - D_DIM);

    const __nv_bfloat16* Aseg[3] = {
        g_xhi + (size_t)mBase * K_DIM,
        g_xlo + (size_t)mBase * K_DIM,
        g_xhi + (size_t)mBase * K_DIM };
    const __nv_bfloat16* Bseg[3] = {
        g_whi + (size_t)nBase * K_DIM,
        g_whi + (size_t)nBase * K_DIM,
        g_wlo + (size_t)nBase * K_DIM };

    float acc[4][4][4];
#pragma unroll
    for (int i = 0; i < 4; ++i)
#pragma unroll
        for (int j = 0; j < 4; ++j)
#pragma unroll
            for (int q = 0; q < 4; ++q) acc[i][j][q] = 0.0f;

    // per-lane ldmatrix params: lane group g -> (row +8*(g&1), kblk + (g>>1))
    const int g = l >> 3, rw = l & 7;
    uint32_t rowAoff[4], swA[4];
#pragma unroll
    for (int mf = 0; mf < 4; ++mf) {
        int r = warpM + mf * 16 + (g & 1) * 8 + rw;
        rowAoff[mf] = (uint32_t)r * 64;        // r*4 chunks * 16B
        swA[mf] = (uint32_t)((r >> 1) & 3);
    }
    uint32_t rowBoff[2], swB[2];
#pragma unroll
    for (int p = 0; p < 2; ++p) {
        int r = warpN + p * 16 + (g & 1) * 8 + rw;
        rowBoff[p] = (uint32_t)r * 64;
        swB[p] = (uint32_t)((r >> 1) & 3);
    }
    const int kb_g = g >> 1;

    load_stage(smBase, 0, Aseg[0], Bseg[0], tid);
    load_stage(smBase, 1, Aseg[0] + 32, Bseg[0] + 32, tid);

    for (int kk = 0; kk < NKK; ++kk) {
        const int slot = kk % 3;
        if (kk < NKK - 1) asm volatile("cp.async.wait_group 1;" ::: "memory");
        else              asm volatile("cp.async.wait_group 0;" ::: "memory");
        __syncthreads();

        const int kn = kk + 2;
        if (kn < NKK) {
            const int s = kn >> 5, ko = (kn & 31) * 32;
            load_stage(smBase, kn % 3, Aseg[s] + ko, Bseg[s] + ko, tid);
        }

        const uint32_t sA = smBase + (uint32_t)slot * STAGE_BYTES;
        const uint32_t sB = sA + ASTG;
#pragma unroll
        for (int h = 0; h < 2; ++h) {
            const uint32_t kb = (uint32_t)(h * 2 + kb_g);
            uint32_t a[4][4], b[2][4];
#pragma unroll
            for (int mf = 0; mf < 4; ++mf)
                LDSM4(a[mf], sA + rowAoff[mf] + ((kb ^ swA[mf]) << 4));
#pragma unroll
            for (int p = 0; p < 2; ++p)
                LDSM4(b[p], sB + rowBoff[p] + ((kb ^ swB[p]) << 4));
#pragma unroll
            for (int mf = 0; mf < 4; ++mf)
#pragma unroll
                for (int nf = 0; nf < 4; ++nf) {
                    const int p = nf >> 1, sub = nf & 1;
                    MMA16816(acc[mf][nf], a[mf], b[p][sub], b[p][sub + 2]);
                }
        }
    }

    // epilogue: bias (+sigmoid for alpha half) -> g_alpha / g_v
    const float* __restrict__ bias = isA ? b_alpha : b_v;
    float* __restrict__ dst = isA ? g_alpha : g_v;

    float bvv[4][2];
#pragma unroll
    for (int nf = 0; nf < 4; ++nf) {
        const int c = ncol0 + warpN + nf * 8 + (l & 3) * 2;
        bvv[nf][0] = bias[c];
        bvv[nf][1] = bias[c + 1];
    }

#pragma unroll
    for (int mf = 0; mf < 4; ++mf) {
        const int r0 = mBase + warpM + mf * 16 + (l >> 2);
#pragma unroll
        for (int hh = 0; hh < 2; ++hh) {
            float* rowp = dst + (size_t)(r0 + hh * 8) * D_DIM;
#pragma unroll
            for (int nf = 0; nf < 4; ++nf) {
                float v0 = acc[mf][nf][hh * 2 + 0] + bvv[nf][0];
                float v1 = acc[mf][nf][hh * 2 + 1] + bvv[nf][1];
                if (isA) { v0 = fast_sigmoid(v0); v1 = fast_sigmoid(v1); }
                float2 st; st.x = v0; st.y = v1;
                *(float2*)(rowp + ncol0 + warpN + nf * 8 + (l & 3) * 2) = st;
            }
        }
    }
}

// ---------------- segmented scan ----------------
__global__ __launch_bounds__(256) void scan_pass1_kernel() {
    const int idx = blockIdx.x * 256 + threadIdx.x;      // seg*C + ch
    const int ch = idx & (C_DIM - 1);
    const int s = idx >> 13;
    const float* __restrict__ A = g_alpha + (size_t)s * SLEN * C_DIM + ch;
    const float* __restrict__ V = g_v + (size_t)s * SLEN * C_DIM + ch;
    float P = 1.0f, Q = 0.0f;
#pragma unroll 8
    for (int i = 0; i < SLEN; ++i) {
        float a = A[(size_t)i * C_DIM];
        float v = V[(size_t)i * C_DIM];
        P *= a;
        Q = fmaf(a, Q - v, v);
    }
    g_P[idx] = P;
    g_Q[idx] = Q;
}

__global__ __launch_bounds__(256) void scan_mid_kernel(const float* __restrict__ h0,
                                                       float* __restrict__ hs, int write_h) {
    const int ch = blockIdx.x * 256 + threadIdx.x;
    float h = h0[ch];
    g_hb[ch] = h;
    if (write_h) hs[ch] = h;
#pragma unroll
    for (int s = 0; s < SEG; ++s) {
        h = fmaf(g_P[s * C_DIM + ch], h, g_Q[s * C_DIM + ch]);
        g_hb[(s + 1) * C_DIM + ch] = h;
    }
}

__global__ __launch_bounds__(256) void scan_pass2_kernel(float* __restrict__ out,
                                                         float* __restrict__ hs, int write_h) {
    const int idx = blockIdx.x * 256 + threadIdx.x;
    const int ch = idx & (C_DIM - 1);
    const int s = idx >> 13;
    const size_t base = (size_t)s * SLEN * C_DIM + ch;
    const float* __restrict__ A = g_alpha + base;
    const float* __restrict__ V = g_v + base;
    float h = g_hb[s * C_DIM + ch];
#pragma unroll 8
    for (int i = 0; i < SLEN; ++i) {
        float a = A[(size_t)i * C_DIM];
        float v = V[(size_t)i * C_DIM];
        h = fmaf(a, h - v, v);
        float sil = __fdividef(h, 1.0f + __expf(-h));   // silu(h)
        out[base + (size_t)i * C_DIM] = h * sil;
        if (write_h) hs[base + (size_t)(i + 1) * C_DIM] = h;
    }
}

// ---------------- launch ----------------
extern "C" void kernel_launch(void* const* d_in, const int* in_sizes, int n_in,
                              void* d_out, int out_size) {
    const float* x  = (const float*)d_in[0];
    const float* h0 = (const float*)d_in[1];
    const float* Wa = (const float*)d_in[2];
    const float* ba = (const float*)d_in[3];
    const float* Wv = (const float*)d_in[4];
    const float* bv = (const float*)d_in[5];

    float* out = (float*)d_out;
    const long long out_elems = (long long)T_DIM * C_DIM;
    const long long h_elems = (long long)(T_DIM + 1) * C_DIM;
    const int write_h = (out_size >= (long long)(out_elems + h_elems)) ? 1 : 0;
    float* hs = out + out_elems;

    split_x_kernel<<<(M_DIM * K_DIM) / 1024, 256>>>(x);
    split_w_kernel<<<(N_DIM * K_DIM) / 1024, 256>>>(Wa, Wv);

    cudaFuncSetAttribute(gemm_hmma_kernel, cudaFuncAttributeMaxDynamicSharedMemorySize, GSMEM);
    gemm_hmma_kernel<<<dim3(N_DIM / 128, M_DIM / 128), 256, GSMEM>>>(ba, bv);

    scan_pass1_kernel<<<(SEG * C_DIM) / 256, 256>>>();
    scan_mid_kernel<<<C_DIM / 256, 256>>>(h0, hs, write_h);
    scan_pass2_kernel<<<(SEG * C_DIM) / 256, 256>>>(out, hs, write_h);
}

// round 4
// speedup vs baseline: 5.1096x; 1.3866x over previous
#include <cuda_runtime.h>
#include <cuda_fp16.h>
#include <cstdint>

#define T_DIM 2048
#define B_DIM 8
#define D_DIM 1024
#define C_DIM 8192              // B*D channels
#define M_DIM 16384             // T*B gemm rows
#define N_DIM 2048              // alpha|v concat
#define K_DIM 1024

#define SEG 32
#define SLEN 64                 // T / SEG

// ---------------- device scratch ----------------
__device__ float g_alpha[(size_t)M_DIM * D_DIM];
__device__ float g_v[(size_t)M_DIM * D_DIM];
__device__ __half g_xhi[(size_t)M_DIM * K_DIM];
__device__ __half g_xlo[(size_t)M_DIM * K_DIM];
__device__ __half g_w[(size_t)N_DIM * K_DIM];
__device__ float g_P[SEG * C_DIM];
__device__ float g_Q[SEG * C_DIM];
__device__ float g_hb[(SEG + 1) * C_DIM];

// ---------------- helpers ----------------
__device__ __forceinline__ uint32_t smem_u32(const void* p) {
    uint32_t a;
    asm("{ .reg .u64 t; cvta.to.shared.u64 t, %1; cvt.u32.u64 %0, t; }" : "=r"(a) : "l"(p));
    return a;
}

__device__ __forceinline__ float fast_sigmoid(float z) {
    return __fdividef(1.0f, 1.0f + __expf(-z));
}

#define LDSM4(r, addr) \
    asm volatile("ldmatrix.sync.aligned.m8n8.x4.shared.b16 {%0,%1,%2,%3}, [%4];" \
        : "=r"((r)[0]), "=r"((r)[1]), "=r"((r)[2]), "=r"((r)[3]) : "r"(addr))

#define MMA16816(c, a, b0, b1) \
    asm volatile("mma.sync.aligned.m16n8k16.row.col.f32.f16.f16.f32 " \
        "{%0,%1,%2,%3}, {%4,%5,%6,%7}, {%8,%9}, {%0,%1,%2,%3};" \
        : "+f"((c)[0]), "+f"((c)[1]), "+f"((c)[2]), "+f"((c)[3]) \
        : "r"((a)[0]), "r"((a)[1]), "r"((a)[2]), "r"((a)[3]), "r"(b0), "r"(b1))

// ---------------- split kernels ----------------
// x -> fp16 hi + lo (hi+lo exact to ~22 mantissa bits)
__global__ __launch_bounds__(256) void split_x_kernel(const float* __restrict__ x) {
    size_t i = ((size_t)blockIdx.x * 256 + threadIdx.x) * 4;
    float4 f = *(const float4*)(x + i);
    __half h0 = __float2half_rn(f.x), h1 = __float2half_rn(f.y);
    __half h2 = __float2half_rn(f.z), h3 = __float2half_rn(f.w);
    __half l0 = __float2half_rn(f.x - __half2float(h0));
    __half l1 = __float2half_rn(f.y - __half2float(h1));
    __half l2 = __float2half_rn(f.z - __half2float(h2));
    __half l3 = __float2half_rn(f.w - __half2float(h3));
    __half2* H = (__half2*)(g_xhi + i);
    __half2* L = (__half2*)(g_xlo + i);
    H[0] = __halves2half2(h0, h1);
    H[1] = __halves2half2(h2, h3);
    L[0] = __halves2half2(l0, l1);
    L[1] = __halves2half2(l2, l3);
}

// W -> single fp16 (concat alpha|v)
__global__ __launch_bounds__(256) void split_w_kernel(const float* __restrict__ Wa,
                                                      const float* __restrict__ Wv) {
    size_t i = ((size_t)blockIdx.x * 256 + threadIdx.x) * 4;
    size_t n = i >> 10;
    const float* src = (n < D_DIM) ? (Wa + i) : (Wv + (i - (size_t)D_DIM * K_DIM));
    float4 f = *(const float4*)src;
    __half2* H = (__half2*)(g_w + i);
    H[0] = __halves2half2(__float2half_rn(f.x), __float2half_rn(f.y));
    H[1] = __halves2half2(__float2half_rn(f.z), __float2half_rn(f.w));
}

// ---------------- HMMA GEMM ----------------
// C[m,n] = xhi*W + xlo*W (fp16 inputs, fp32 accum), 2 K-segments.
// BM=128, BN=128, BK=32, 256 threads (8 warps, 64x32 warp tiles), 3-stage cp.async.
#define BK 32
#define NKK 64                       // 2 segments * (1024/32)
#define ASTG (128 * BK * 2)          // 8192 B
#define STAGE_BYTES (2 * ASTG)       // A + B = 16384 B
#define GSMEM (3 * STAGE_BYTES + 128)

// smem chunk index (16B units) with xor swizzle for conflict-free LDSM
__device__ __forceinline__ uint32_t chunk_off(int r, int kb) {
    return (uint32_t)((r * 4 + (kb ^ ((r >> 1) & 3))) * 16);
}

__device__ __forceinline__ void load_stage(uint32_t smBase, int slot,
                                           const __half* Asrc,
                                           const __half* Bsrc, int tid) {
    uint32_t sA = smBase + (uint32_t)slot * STAGE_BYTES;
    uint32_t sB = sA + ASTG;
#pragma unroll
    for (int j = 0; j < 2; ++j) {
        int idx = tid + j * 256;
        int r = idx >> 2, cb = idx & 3;
        const char* gp = (const char*)(Asrc + (size_t)r * K_DIM) + cb * 16;
        asm volatile("cp.async.cg.shared.global [%0], [%1], 16;"
                     :: "r"(sA + chunk_off(r, cb)), "l"(gp));
    }
#pragma unroll
    for (int j = 0; j < 2; ++j) {
        int idx = tid + j * 256;
        int r = idx >> 2, cb = idx & 3;
        const char* gp = (const char*)(Bsrc + (size_t)r * K_DIM) + cb * 16;
        asm volatile("cp.async.cg.shared.global [%0], [%1], 16;"
                     :: "r"(sB + chunk_off(r, cb)), "l"(gp));
    }
    asm volatile("cp.async.commit_group;" ::: "memory");
}

__global__ __launch_bounds__(256, 2)
void gemm_hmma_kernel(const float* __restrict__ b_alpha, const float* __restrict__ b_v) {
    extern __shared__ char smem[];
    uint32_t smBase = (smem_u32(smem) + 127u) & ~127u;

    const int tid = threadIdx.x;
    const int l = tid & 31, wid = tid >> 5;
    const int warpM = (wid & 1) * 64;
    const int warpN = (wid >> 1) * 32;
    const int mBase = blockIdx.y * 128;
    const int nBase = blockIdx.x * 128;
    const bool isA = (nBase < D_DIM);
    const int ncol0 = isA ? nBase : (nBase - D_DIM);

    const __half* Aseg[2] = {
        g_xhi + (size_t)mBase * K_DIM,
        g_xlo + (size_t)mBase * K_DIM };
    const __half* Bw = g_w + (size_t)nBase * K_DIM;

    float acc[4][4][4];
#pragma unroll
    for (int i = 0; i < 4; ++i)
#pragma unroll
        for (int j = 0; j < 4; ++j)
#pragma unroll
            for (int q = 0; q < 4; ++q) acc[i][j][q] = 0.0f;

    // per-lane ldmatrix params: lane group g -> (row +8*(g&1), kblk + (g>>1))
    const int g = l >> 3, rw = l & 7;
    uint32_t rowAoff[4], swA[4];
#pragma unroll
    for (int mf = 0; mf < 4; ++mf) {
        int r = warpM + mf * 16 + (g & 1) * 8 + rw;
        rowAoff[mf] = (uint32_t)r * 64;        // r*4 chunks * 16B
        swA[mf] = (uint32_t)((r >> 1) & 3);
    }
    uint32_t rowBoff[2], swB[2];
#pragma unroll
    for (int p = 0; p < 2; ++p) {
        int r = warpN + p * 16 + (g & 1) * 8 + rw;
        rowBoff[p] = (uint32_t)r * 64;
        swB[p] = (uint32_t)((r >> 1) & 3);
    }
    const int kb_g = g >> 1;

    load_stage(smBase, 0, Aseg[0], Bw, tid);
    load_stage(smBase, 1, Aseg[0] + 32, Bw + 32, tid);

    for (int kk = 0; kk < NKK; ++kk) {
        const int slot = kk % 3;
        if (kk < NKK - 1) asm volatile("cp.async.wait_group 1;" ::: "memory");
        else              asm volatile("cp.async.wait_group 0;" ::: "memory");
        __syncthreads();

        const int kn = kk + 2;
        if (kn < NKK) {
            const int s = kn >> 5, ko = (kn & 31) * 32;
            load_stage(smBase, kn % 3, Aseg[s] + ko, Bw + ko, tid);
        }

        const uint32_t sA = smBase + (uint32_t)slot * STAGE_BYTES;
        const uint32_t sB = sA + ASTG;
#pragma unroll
        for (int h = 0; h < 2; ++h) {
            const uint32_t kb = (uint32_t)(h * 2 + kb_g);
            uint32_t a[4][4], b[2][4];
#pragma unroll
            for (int mf = 0; mf < 4; ++mf)
                LDSM4(a[mf], sA + rowAoff[mf] + ((kb ^ swA[mf]) << 4));
#pragma unroll
            for (int p = 0; p < 2; ++p)
                LDSM4(b[p], sB + rowBoff[p] + ((kb ^ swB[p]) << 4));
#pragma unroll
            for (int mf = 0; mf < 4; ++mf)
#pragma unroll
                for (int nf = 0; nf < 4; ++nf) {
                    const int p = nf >> 1, sub = nf & 1;
                    MMA16816(acc[mf][nf], a[mf], b[p][sub], b[p][sub + 2]);
                }
        }
    }

    // epilogue: bias (+sigmoid for alpha half) -> g_alpha / g_v
    const float* __restrict__ bias = isA ? b_alpha : b_v;
    float* __restrict__ dst = isA ? g_alpha : g_v;

    float bvv[4][2];
#pragma unroll
    for (int nf = 0; nf < 4; ++nf) {
        const int c = ncol0 + warpN + nf * 8 + (l & 3) * 2;
        bvv[nf][0] = bias[c];
        bvv[nf][1] = bias[c + 1];
    }

#pragma unroll
    for (int mf = 0; mf < 4; ++mf) {
        const int r0 = mBase + warpM + mf * 16 + (l >> 2);
#pragma unroll
        for (int hh = 0; hh < 2; ++hh) {
            float* rowp = dst + (size_t)(r0 + hh * 8) * D_DIM;
#pragma unroll
            for (int nf = 0; nf < 4; ++nf) {
                float v0 = acc[mf][nf][hh * 2 + 0] + bvv[nf][0];
                float v1 = acc[mf][nf][hh * 2 + 1] + bvv[nf][1];
                if (isA) { v0 = fast_sigmoid(v0); v1 = fast_sigmoid(v1); }
                float2 st; st.x = v0; st.y = v1;
                *(float2*)(rowp + ncol0 + warpN + nf * 8 + (l & 3) * 2) = st;
            }
        }
    }
}

// ---------------- segmented scan ----------------
__global__ __launch_bounds__(256) void scan_pass1_kernel() {
    const int idx = blockIdx.x * 256 + threadIdx.x;      // seg*C + ch
    const int ch = idx & (C_DIM - 1);
    const int s = idx >> 13;
    const float* __restrict__ A = g_alpha + (size_t)s * SLEN * C_DIM + ch;
    const float* __restrict__ V = g_v + (size_t)s * SLEN * C_DIM + ch;
    float P = 1.0f, Q = 0.0f;
#pragma unroll 8
    for (int i = 0; i < SLEN; ++i) {
        float a = A[(size_t)i * C_DIM];
        float v = V[(size_t)i * C_DIM];
        P *= a;
        Q = fmaf(a, Q - v, v);
    }
    g_P[idx] = P;
    g_Q[idx] = Q;
}

__global__ __launch_bounds__(256) void scan_mid_kernel(const float* __restrict__ h0,
                                                       float* __restrict__ hs, int write_h) {
    const int ch = blockIdx.x * 256 + threadIdx.x;
    float h = h0[ch];
    g_hb[ch] = h;
    if (write_h) hs[ch] = h;
#pragma unroll
    for (int s = 0; s < SEG; ++s) {
        h = fmaf(g_P[s * C_DIM + ch], h, g_Q[s * C_DIM + ch]);
        g_hb[(s + 1) * C_DIM + ch] = h;
    }
}

__global__ __launch_bounds__(256) void scan_pass2_kernel(float* __restrict__ out,
                                                         float* __restrict__ hs, int write_h) {
    const int idx = blockIdx.x * 256 + threadIdx.x;
    const int ch = idx & (C_DIM - 1);
    const int s = idx >> 13;
    const size_t base = (size_t)s * SLEN * C_DIM + ch;
    const float* __restrict__ A = g_alpha + base;
    const float* __restrict__ V = g_v + base;
    float h = g_hb[s * C_DIM + ch];
#pragma unroll 8
    for (int i = 0; i < SLEN; ++i) {
        float a = A[(size_t)i * C_DIM];
        float v = V[(size_t)i * C_DIM];
        h = fmaf(a, h - v, v);
        float sil = __fdividef(h, 1.0f + __expf(-h));   // silu(h)
        out[base + (size_t)i * C_DIM] = h * sil;
        if (write_h) hs[base + (size_t)(i + 1) * C_DIM] = h;
    }
}

// ---------------- launch ----------------
extern "C" void kernel_launch(void* const* d_in, const int* in_sizes, int n_in,
                              void* d_out, int out_size) {
    const float* x  = (const float*)d_in[0];
    const float* h0 = (const float*)d_in[1];
    const float* Wa = (const float*)d_in[2];
    const float* ba = (const float*)d_in[3];
    const float* Wv = (const float*)d_in[4];
    const float* bv = (const float*)d_in[5];

    float* out = (float*)d_out;
    const long long out_elems = (long long)T_DIM * C_DIM;
    const long long h_elems = (long long)(T_DIM + 1) * C_DIM;
    const int write_h = (out_size >= (long long)(out_elems + h_elems)) ? 1 : 0;
    float* hs = out + out_elems;

    split_x_kernel<<<(M_DIM * K_DIM) / 1024, 256>>>(x);
    split_w_kernel<<<(N_DIM * K_DIM) / 1024, 256>>>(Wa, Wv);

    cudaFuncSetAttribute(gemm_hmma_kernel, cudaFuncAttributeMaxDynamicSharedMemorySize, GSMEM);
    gemm_hmma_kernel<<<dim3(N_DIM / 128, M_DIM / 128), 256, GSMEM>>>(ba, bv);

    scan_pass1_kernel<<<(SEG * C_DIM) / 256, 256>>>();
    scan_mid_kernel<<<C_DIM / 256, 256>>>(h0, hs, write_h);
    scan_pass2_kernel<<<(SEG * C_DIM) / 256, 256>>>(out, hs, write_h);
}

// round 5
// speedup vs baseline: 8.3177x; 1.6279x over previous
#include <cuda_runtime.h>
#include <cuda_fp16.h>
#include <cstdint>

#define T_DIM 2048
#define B_DIM 8
#define D_DIM 1024
#define C_DIM 8192              // B*D channels
#define M_DIM 16384             // T*B gemm rows
#define N_DIM 2048              // alpha|v concat
#define K_DIM 1024

#define SEG 32
#define SLEN 64                 // T / SEG

// ---------------- device scratch ----------------
__device__ float g_alpha[(size_t)M_DIM * D_DIM];
__device__ float g_v[(size_t)M_DIM * D_DIM];
__device__ __half g_xh[(size_t)M_DIM * K_DIM];
__device__ __half g_w[(size_t)N_DIM * K_DIM];
__device__ float g_P[SEG * C_DIM];
__device__ float g_Q[SEG * C_DIM];
__device__ float g_hb[(SEG + 1) * C_DIM];

// ---------------- helpers ----------------
__device__ __forceinline__ uint32_t smem_u32(const void* p) {
    uint32_t a;
    asm("{ .reg .u64 t; cvta.to.shared.u64 t, %1; cvt.u32.u64 %0, t; }" : "=r"(a) : "l"(p));
    return a;
}

__device__ __forceinline__ float fast_sigmoid(float z) {
    return __fdividef(1.0f, 1.0f + __expf(-z));
}

#define LDSM4(r, addr) \
    asm volatile("ldmatrix.sync.aligned.m8n8.x4.shared.b16 {%0,%1,%2,%3}, [%4];" \
        : "=r"((r)[0]), "=r"((r)[1]), "=r"((r)[2]), "=r"((r)[3]) : "r"(addr))

#define MMA16816(c, a, b0, b1) \
    asm volatile("mma.sync.aligned.m16n8k16.row.col.f32.f16.f16.f32 " \
        "{%0,%1,%2,%3}, {%4,%5,%6,%7}, {%8,%9}, {%0,%1,%2,%3};" \
        : "+f"((c)[0]), "+f"((c)[1]), "+f"((c)[2]), "+f"((c)[3]) \
        : "r"((a)[0]), "r"((a)[1]), "r"((a)[2]), "r"((a)[3]), "r"(b0), "r"(b1))

// ---------------- convert kernels (f32 -> fp16) ----------------
__global__ __launch_bounds__(256) void conv_x_kernel(const float* __restrict__ x) {
    size_t i = ((size_t)blockIdx.x * 256 + threadIdx.x) * 4;
    float4 f = *(const float4*)(x + i);
    __half2* H = (__half2*)(g_xh + i);
    H[0] = __halves2half2(__float2half_rn(f.x), __float2half_rn(f.y));
    H[1] = __halves2half2(__float2half_rn(f.z), __float2half_rn(f.w));
}

__global__ __launch_bounds__(256) void conv_w_kernel(const float* __restrict__ Wa,
                                                     const float* __restrict__ Wv) {
    size_t i = ((size_t)blockIdx.x * 256 + threadIdx.x) * 4;
    size_t n = i >> 10;
    const float* src = (n < D_DIM) ? (Wa + i) : (Wv + (i - (size_t)D_DIM * K_DIM));
    float4 f = *(const float4*)src;
    __half2* H = (__half2*)(g_w + i);
    H[0] = __halves2half2(__float2half_rn(f.x), __float2half_rn(f.y));
    H[1] = __halves2half2(__float2half_rn(f.z), __float2half_rn(f.w));
}

// ---------------- HMMA GEMM ----------------
// C[m,n] = x*W (fp16 inputs, fp32 accum), single pass.
// BM=128, BN=128, BK=32, 256 threads (8 warps, 64x32 warp tiles), 3-stage cp.async.
#define BK 32
#define NKK 32                       // 1024/32
#define ASTG (128 * BK * 2)          // 8192 B
#define STAGE_BYTES (2 * ASTG)       // A + B = 16384 B
#define GSMEM (3 * STAGE_BYTES + 128)

// smem chunk index (16B units) with xor swizzle for conflict-free LDSM
__device__ __forceinline__ uint32_t chunk_off(int r, int kb) {
    return (uint32_t)((r * 4 + (kb ^ ((r >> 1) & 3))) * 16);
}

__device__ __forceinline__ void load_stage(uint32_t smBase, int slot,
                                           const __half* Asrc,
                                           const __half* Bsrc, int tid) {
    uint32_t sA = smBase + (uint32_t)slot * STAGE_BYTES;
    uint32_t sB = sA + ASTG;
#pragma unroll
    for (int j = 0; j < 2; ++j) {
        int idx = tid + j * 256;
        int r = idx >> 2, cb = idx & 3;
        const char* gp = (const char*)(Asrc + (size_t)r * K_DIM) + cb * 16;
        asm volatile("cp.async.cg.shared.global [%0], [%1], 16;"
                     :: "r"(sA + chunk_off(r, cb)), "l"(gp));
    }
#pragma unroll
    for (int j = 0; j < 2; ++j) {
        int idx = tid + j * 256;
        int r = idx >> 2, cb = idx & 3;
        const char* gp = (const char*)(Bsrc + (size_t)r * K_DIM) + cb * 16;
        asm volatile("cp.async.cg.shared.global [%0], [%1], 16;"
                     :: "r"(sB + chunk_off(r, cb)), "l"(gp));
    }
    asm volatile("cp.async.commit_group;" ::: "memory");
}

__global__ __launch_bounds__(256, 2)
void gemm_hmma_kernel(const float* __restrict__ b_alpha, const float* __restrict__ b_v) {
    extern __shared__ char smem[];
    uint32_t smBase = (smem_u32(smem) + 127u) & ~127u;

    const int tid = threadIdx.x;
    const int l = tid & 31, wid = tid >> 5;
    const int warpM = (wid & 1) * 64;
    const int warpN = (wid >> 1) * 32;
    const int mBase = blockIdx.y * 128;
    const int nBase = blockIdx.x * 128;
    const bool isA = (nBase < D_DIM);
    const int ncol0 = isA ? nBase : (nBase - D_DIM);

    const __half* Ax = g_xh + (size_t)mBase * K_DIM;
    const __half* Bw = g_w + (size_t)nBase * K_DIM;

    float acc[4][4][4];
#pragma unroll
    for (int i = 0; i < 4; ++i)
#pragma unroll
        for (int j = 0; j < 4; ++j)
#pragma unroll
            for (int q = 0; q < 4; ++q) acc[i][j][q] = 0.0f;

    // per-lane ldmatrix params: lane group g -> (row +8*(g&1), kblk + (g>>1))
    const int g = l >> 3, rw = l & 7;
    uint32_t rowAoff[4], swA[4];
#pragma unroll
    for (int mf = 0; mf < 4; ++mf) {
        int r = warpM + mf * 16 + (g & 1) * 8 + rw;
        rowAoff[mf] = (uint32_t)r * 64;        // r*4 chunks * 16B
        swA[mf] = (uint32_t)((r >> 1) & 3);
    }
    uint32_t rowBoff[2], swB[2];
#pragma unroll
    for (int p = 0; p < 2; ++p) {
        int r = warpN + p * 16 + (g & 1) * 8 + rw;
        rowBoff[p] = (uint32_t)r * 64;
        swB[p] = (uint32_t)((r >> 1) & 3);
    }
    const int kb_g = g >> 1;

    load_stage(smBase, 0, Ax, Bw, tid);
    load_stage(smBase, 1, Ax + 32, Bw + 32, tid);

    for (int kk = 0; kk < NKK; ++kk) {
        const int slot = kk % 3;
        if (kk < NKK - 1) asm volatile("cp.async.wait_group 1;" ::: "memory");
        else              asm volatile("cp.async.wait_group 0;" ::: "memory");
        __syncthreads();

        const int kn = kk + 2;
        if (kn < NKK) {
            const int ko = kn * 32;
            load_stage(smBase, kn % 3, Ax + ko, Bw + ko, tid);
        }

        const uint32_t sA = smBase + (uint32_t)slot * STAGE_BYTES;
        const uint32_t sB = sA + ASTG;
#pragma unroll
        for (int h = 0; h < 2; ++h) {
            const uint32_t kb = (uint32_t)(h * 2 + kb_g);
            uint32_t a[4][4], b[2][4];
#pragma unroll
            for (int mf = 0; mf < 4; ++mf)
                LDSM4(a[mf], sA + rowAoff[mf] + ((kb ^ swA[mf]) << 4));
#pragma unroll
            for (int p = 0; p < 2; ++p)
                LDSM4(b[p], sB + rowBoff[p] + ((kb ^ swB[p]) << 4));
#pragma unroll
            for (int mf = 0; mf < 4; ++mf)
#pragma unroll
                for (int nf = 0; nf < 4; ++nf) {
                    const int p = nf >> 1, sub = nf & 1;
                    MMA16816(acc[mf][nf], a[mf], b[p][sub], b[p][sub + 2]);
                }
        }
    }

    // epilogue: bias (+sigmoid for alpha half) -> g_alpha / g_v
    const float* __restrict__ bias = isA ? b_alpha : b_v;
    float* __restrict__ dst = isA ? g_alpha : g_v;

    float bvv[4][2];
#pragma unroll
    for (int nf = 0; nf < 4; ++nf) {
        const int c = ncol0 + warpN + nf * 8 + (l & 3) * 2;
        bvv[nf][0] = bias[c];
        bvv[nf][1] = bias[c + 1];
    }

#pragma unroll
    for (int mf = 0; mf < 4; ++mf) {
        const int r0 = mBase + warpM + mf * 16 + (l >> 2);
#pragma unroll
        for (int hh = 0; hh < 2; ++hh) {
            float* rowp = dst + (size_t)(r0 + hh * 8) * D_DIM;
#pragma unroll
            for (int nf = 0; nf < 4; ++nf) {
                float v0 = acc[mf][nf][hh * 2 + 0] + bvv[nf][0];
                float v1 = acc[mf][nf][hh * 2 + 1] + bvv[nf][1];
                if (isA) { v0 = fast_sigmoid(v0); v1 = fast_sigmoid(v1); }
                float2 st; st.x = v0; st.y = v1;
                *(float2*)(rowp + ncol0 + warpN + nf * 8 + (l & 3) * 2) = st;
            }
        }
    }
}

// ---------------- segmented scan ----------------
__global__ __launch_bounds__(256) void scan_pass1_kernel() {
    const int idx = blockIdx.x * 256 + threadIdx.x;      // seg*C + ch
    const int ch = idx & (C_DIM - 1);
    const int s = idx >> 13;
    const float* __restrict__ A = g_alpha + (size_t)s * SLEN * C_DIM + ch;
    const float* __restrict__ V = g_v + (size_t)s * SLEN * C_DIM + ch;
    float P = 1.0f, Q = 0.0f;
#pragma unroll 8
    for (int i = 0; i < SLEN; ++i) {
        float a = A[(size_t)i * C_DIM];
        float v = V[(size_t)i * C_DIM];
        P *= a;
        Q = fmaf(a, Q - v, v);
    }
    g_P[idx] = P;
    g_Q[idx] = Q;
}

__global__ __launch_bounds__(256) void scan_mid_kernel(const float* __restrict__ h0,
                                                       float* __restrict__ hs, int write_h) {
    const int ch = blockIdx.x * 256 + threadIdx.x;
    float h = h0[ch];
    g_hb[ch] = h;
    if (write_h) hs[ch] = h;
#pragma unroll
    for (int s = 0; s < SEG; ++s) {
        h = fmaf(g_P[s * C_DIM + ch], h, g_Q[s * C_DIM + ch]);
        g_hb[(s + 1) * C_DIM + ch] = h;
    }
}

__global__ __launch_bounds__(256) void scan_pass2_kernel(float* __restrict__ out,
                                                         float* __restrict__ hs, int write_h) {
    const int idx = blockIdx.x * 256 + threadIdx.x;
    const int ch = idx & (C_DIM - 1);
    const int s = idx >> 13;
    const size_t base = (size_t)s * SLEN * C_DIM + ch;
    const float* __restrict__ A = g_alpha + base;
    const float* __restrict__ V = g_v + base;
    float h = g_hb[s * C_DIM + ch];
#pragma unroll 8
    for (int i = 0; i < SLEN; ++i) {
        float a = A[(size_t)i * C_DIM];
        float v = V[(size_t)i * C_DIM];
        h = fmaf(a, h - v, v);
        float sil = __fdividef(h, 1.0f + __expf(-h));   // silu(h)
        out[base + (size_t)i * C_DIM] = h * sil;
        if (write_h) hs[base + (size_t)(i + 1) * C_DIM] = h;
    }
}

// ---------------- launch ----------------
extern "C" void kernel_launch(void* const* d_in, const int* in_sizes, int n_in,
                              void* d_out, int out_size) {
    const float* x  = (const float*)d_in[0];
    const float* h0 = (const float*)d_in[1];
    const float* Wa = (const float*)d_in[2];
    const float* ba = (const float*)d_in[3];
    const float* Wv = (const float*)d_in[4];
    const float* bv = (const float*)d_in[5];

    float* out = (float*)d_out;
    const long long out_elems = (long long)T_DIM * C_DIM;
    const long long h_elems = (long long)(T_DIM + 1) * C_DIM;
    const int write_h = (out_size >= (long long)(out_elems + h_elems)) ? 1 : 0;
    float* hs = out + out_elems;

    conv_x_kernel<<<(M_DIM * K_DIM) / 1024, 256>>>(x);
    conv_w_kernel<<<(N_DIM * K_DIM) / 1024, 256>>>(Wa, Wv);

    cudaFuncSetAttribute(gemm_hmma_kernel, cudaFuncAttributeMaxDynamicSharedMemorySize, GSMEM);
    gemm_hmma_kernel<<<dim3(N_DIM / 128, M_DIM / 128), 256, GSMEM>>>(ba, bv);

    scan_pass1_kernel<<<(SEG * C_DIM) / 256, 256>>>();
    scan_mid_kernel<<<C_DIM / 256, 256>>>(h0, hs, write_h);
    scan_pass2_kernel<<<(SEG * C_DIM) / 256, 256>>>(out, hs, write_h);
}